// round 7
// baseline (speedup 1.0000x reference)
#include <cuda_runtime.h>
#include <math.h>

#define BATCH 32
#define LQ 1024
#define LA 1024
#define HDIM 512

#define BM 128
#define BN 128
#define BK 32
#define NSTAGE 3
#define LDR 36                 // row-major tile stride (floats): 32 + 4 pad, 16B-aligned rows
#define LDU 132                // U tile [k][n] stride
#define TILE_F (BM * LDR)      // 4608 floats
#define UTILE_F (BK * LDU)     // 4224 floats
#define NKT (HDIM / BK)        // 16

// Scratch (device globals: allocation inside kernel_launch is forbidden)
__device__ float    g_qU[(size_t)BATCH * LQ * HDIM];   // 64 MB (tf32-rounded)
__device__ float    g_qt[(size_t)BATCH * LQ * HDIM];   // 64 MB: tf32-rounded q
__device__ float    g_at[(size_t)BATCH * LA * HDIM];   // 64 MB: tf32-rounded a
__device__ float    g_Ut[(size_t)HDIM * HDIM];         //  1 MB: tf32-rounded U
__device__ float    g_rowAtt[BATCH * LQ];
__device__ unsigned g_colMaxBits[BATCH * LA];          // float bits, values >= 0
__device__ float    g_colSum[BATCH * LA];

// ---------------------------------------------------------------------------
__device__ __forceinline__ unsigned cvt_tf32(float x) {
    unsigned u;
    asm("cvt.rna.tf32.f32 %0, %1;" : "=r"(u) : "f"(x));
    return u;
}

__device__ __forceinline__ void mma_tf32(float* d, const unsigned* a, const unsigned* b) {
    asm volatile(
        "mma.sync.aligned.m16n8k8.row.col.f32.tf32.tf32.f32 "
        "{%0,%1,%2,%3}, {%4,%5,%6,%7}, {%8,%9}, {%0,%1,%2,%3};\n"
        : "+f"(d[0]), "+f"(d[1]), "+f"(d[2]), "+f"(d[3])
        : "r"(a[0]), "r"(a[1]), "r"(a[2]), "r"(a[3]), "r"(b[0]), "r"(b[1]));
}

__device__ __forceinline__ void cp_async16(float* smem_ptr, const float* gmem) {
    unsigned s = (unsigned)__cvta_generic_to_shared(smem_ptr);
    asm volatile("cp.async.cg.shared.global [%0], [%1], 16;\n" :: "r"(s), "l"(gmem));
}
#define CP_COMMIT() asm volatile("cp.async.commit_group;\n" ::: "memory")
#define CP_WAIT1()  asm volatile("cp.async.wait_group 1;\n" ::: "memory")

// Row-major tile load: 128 rows x 32 floats (ld = HDIM), 256 threads x 4 chunks of 16B
__device__ __forceinline__ void load_rows_async(float* sm, const float* g, int tid) {
    #pragma unroll
    for (int i = 0; i < 4; i++) {
        int c = tid + i * 256;         // 0..1023
        int row = c >> 3, kc = c & 7;  // 8 chunks per row
        cp_async16(sm + row * LDR + kc * 4, g + (size_t)row * HDIM + kc * 4);
    }
}

// U tile load: 32 rows(k) x 128 floats(n) (ld = HDIM)
__device__ __forceinline__ void load_U_async(float* sm, const float* g, int tid) {
    #pragma unroll
    for (int i = 0; i < 4; i++) {
        int c = tid + i * 256;
        int k = c >> 5, nc = c & 31;   // 32 chunks per row
        cp_async16(sm + k * LDU + nc * 4, g + (size_t)k * HDIM + nc * 4);
    }
}

// mma over one BK tile, both operands row-major [row][k], data pre-rounded to
// tf32 bit patterns (no cvt in the loop). k-permutation: frag k-col c -> data
// k 2c ; c+4 -> 2c+1 (applied to A and B identically; dot product invariant).
__device__ __forceinline__ void compute_rr(const float* sA, const float* sB,
                                           float acc[4][4][4], int wm, int wn, int lane) {
    const int c2 = 2 * (lane & 3);
    const int g4 = lane >> 2;
    #pragma unroll
    for (int ks = 0; ks < 4; ks++) {
        const int k2 = ks * 8 + c2;
        unsigned bfr[4][2];
        #pragma unroll
        for (int nt = 0; nt < 4; nt++) {
            int col = wn * 32 + nt * 8 + g4;
            float2 bv = *(const float2*)(sB + col * LDR + k2);
            bfr[nt][0] = __float_as_uint(bv.x);
            bfr[nt][1] = __float_as_uint(bv.y);
        }
        #pragma unroll
        for (int mt = 0; mt < 4; mt++) {
            int row = wm * 64 + mt * 16 + g4;
            float2 lo = *(const float2*)(sA + row * LDR + k2);
            float2 hi = *(const float2*)(sA + (row + 8) * LDR + k2);
            unsigned afr[4] = {__float_as_uint(lo.x), __float_as_uint(hi.x),
                               __float_as_uint(lo.y), __float_as_uint(hi.y)};
            #pragma unroll
            for (int nt = 0; nt < 4; nt++)
                mma_tf32(acc[mt][nt], afr, bfr[nt]);
        }
    }
}

// same but B from U layout [k][n] (bank-conflict-free: bank = 8c + g4)
__device__ __forceinline__ void compute_ru(const float* sA, const float* sU,
                                           float acc[4][4][4], int wm, int wn, int lane) {
    const int c2 = 2 * (lane & 3);
    const int g4 = lane >> 2;
    #pragma unroll
    for (int ks = 0; ks < 4; ks++) {
        const int k2 = ks * 8 + c2;
        unsigned bfr[4][2];
        #pragma unroll
        for (int nt = 0; nt < 4; nt++) {
            int col = wn * 32 + nt * 8 + g4;
            bfr[nt][0] = __float_as_uint(sU[(k2 + 0) * LDU + col]);
            bfr[nt][1] = __float_as_uint(sU[(k2 + 1) * LDU + col]);
        }
        #pragma unroll
        for (int mt = 0; mt < 4; mt++) {
            int row = wm * 64 + mt * 16 + g4;
            float2 lo = *(const float2*)(sA + row * LDR + k2);
            float2 hi = *(const float2*)(sA + (row + 8) * LDR + k2);
            unsigned afr[4] = {__float_as_uint(lo.x), __float_as_uint(hi.x),
                               __float_as_uint(lo.y), __float_as_uint(hi.y)};
            #pragma unroll
            for (int nt = 0; nt < 4; nt++)
                mma_tf32(acc[mt][nt], afr, bfr[nt]);
        }
    }
}

// ---------------------------------------------------------------------------
// Kernel 0a: zero col-stat accumulators and the output buffer
// ---------------------------------------------------------------------------
__global__ void init_stats_kernel(float* out, int out_n) {
    int i = blockIdx.x * blockDim.x + threadIdx.x;
    if (i < BATCH * LA) {
        g_colMaxBits[i] = 0u;
        g_colSum[i] = 0.0f;
    }
    if (i < out_n) out[i] = 0.0f;
}

// ---------------------------------------------------------------------------
// Kernel 0b: pre-round q, a, U to tf32 bit patterns (float4 grid-stride)
// ---------------------------------------------------------------------------
#define NQ4 ((BATCH * LQ * HDIM) / 4)      // 4,194,304
#define NA4 ((BATCH * LA * HDIM) / 4)
#define NU4 ((HDIM * HDIM) / 4)            //    65,536
#define NTOT4 (NQ4 + NA4 + NU4)

__global__ __launch_bounds__(256) void convert_kernel(const float* __restrict__ q,
                                                      const float* __restrict__ a,
                                                      const float* __restrict__ U) {
    int stride = gridDim.x * blockDim.x;
    for (int i = blockIdx.x * blockDim.x + threadIdx.x; i < NTOT4; i += stride) {
        const float4* src;
        float4* dst;
        if (i < NQ4) {
            src = (const float4*)q + i;
            dst = (float4*)g_qt + i;
        } else if (i < NQ4 + NA4) {
            src = (const float4*)a + (i - NQ4);
            dst = (float4*)g_at + (i - NQ4);
        } else {
            src = (const float4*)U + (i - NQ4 - NA4);
            dst = (float4*)g_Ut + (i - NQ4 - NA4);
        }
        float4 v = *src;
        float4 w;
        w.x = __uint_as_float(cvt_tf32(v.x));
        w.y = __uint_as_float(cvt_tf32(v.y));
        w.z = __uint_as_float(cvt_tf32(v.z));
        w.w = __uint_as_float(cvt_tf32(v.w));
        *dst = w;
    }
}

// ---------------------------------------------------------------------------
// Kernel 1: qU = q @ U  (tf32, 3-stage cp.async pipeline, pre-rounded inputs)
// ---------------------------------------------------------------------------
__global__ __launch_bounds__(256, 2) void gemm_qU_tc() {
    extern __shared__ float dsm[];
    float* sA = dsm;                       // [NSTAGE][TILE_F]
    float* sU = dsm + NSTAGE * TILE_F;     // [NSTAGE][UTILE_F]

    const int tid  = threadIdx.x;
    const int lane = tid & 31;
    const int wm   = (tid >> 5) >> 2;
    const int wn   = (tid >> 5) & 3;
    const int m0   = blockIdx.y * BM;
    const int n0   = blockIdx.x * BN;

    const float* gA = g_qt + (size_t)m0 * HDIM;
    const float* gU = g_Ut + n0;

    float acc[4][4][4] = {};

    #pragma unroll
    for (int s = 0; s < NSTAGE - 1; s++) {
        load_rows_async(sA + s * TILE_F, gA + s * BK, tid);
        load_U_async(sU + s * UTILE_F, gU + (size_t)s * BK * HDIM, tid);
        CP_COMMIT();
    }

    for (int kt = 0; kt < NKT; kt++) {
        CP_WAIT1();
        __syncthreads();
        int pf = kt + NSTAGE - 1;
        if (pf < NKT) {
            load_rows_async(sA + (pf % NSTAGE) * TILE_F, gA + pf * BK, tid);
            load_U_async(sU + (pf % NSTAGE) * UTILE_F, gU + (size_t)pf * BK * HDIM, tid);
        }
        CP_COMMIT();
        compute_ru(sA + (kt % NSTAGE) * TILE_F, sU + (kt % NSTAGE) * UTILE_F,
                   acc, wm, wn, lane);
    }

    // epilogue: round to tf32 before store so fused_X needs no cvt
    #pragma unroll
    for (int mt = 0; mt < 4; mt++) {
        int row = m0 + wm * 64 + mt * 16 + (lane >> 2);
        #pragma unroll
        for (int nt = 0; nt < 4; nt++) {
            int col = n0 + wn * 32 + nt * 8 + (lane & 3) * 2;
            *(float2*)(g_qU + (size_t)row * HDIM + col) =
                make_float2(__uint_as_float(cvt_tf32(acc[mt][nt][0])),
                            __uint_as_float(cvt_tf32(acc[mt][nt][1])));
            *(float2*)(g_qU + (size_t)(row + 8) * HDIM + col) =
                make_float2(__uint_as_float(cvt_tf32(acc[mt][nt][2])),
                            __uint_as_float(cvt_tf32(acc[mt][nt][3])));
        }
    }
}

// ---------------------------------------------------------------------------
// Kernel 2: fused X = qU @ a^T + sigmoid/exp + row & col stats
// Flat 128-tile pipeline over (j0 x kt); epilogue every 16 tiles overlaps
// with the next j-tile's in-flight cp.async loads.
// ---------------------------------------------------------------------------
__global__ __launch_bounds__(256, 2) void fused_X_tc(const float* __restrict__ q_mask,
                                                     const float* __restrict__ a_mask) {
    extern __shared__ float dsm[];
    float* sA = dsm;
    float* sB = dsm + NSTAGE * TILE_F;

    const int tid  = threadIdx.x;
    const int lane = tid & 31;
    const int wm   = (tid >> 5) >> 2;
    const int wn   = (tid >> 5) & 3;
    const int b    = blockIdx.y;
    const int i0   = blockIdx.x * BM;

    const float* qUb = g_qU + ((size_t)b * LQ + i0) * HDIM;
    const float* ab  = g_at + (size_t)b * LA * HDIM;

    float qm[4][2];
    #pragma unroll
    for (int mt = 0; mt < 4; mt++) {
        int r = i0 + wm * 64 + mt * 16 + (lane >> 2);
        qm[mt][0] = q_mask[b * LQ + r];
        qm[mt][1] = q_mask[b * LQ + r + 8];
    }

    float rowMax[4][2] = {};
    float rowSum[4][2] = {};
    float acc[4][4][4] = {};

    const int NT = (LA / BN) * NKT;   // 128 total tiles

    #pragma unroll 1
    for (int s = 0; s < NSTAGE - 1; s++) {
        load_rows_async(sA + s * TILE_F, qUb + s * BK, tid);
        load_rows_async(sB + s * TILE_F, ab + s * BK, tid);   // j = 0
        CP_COMMIT();
    }

    for (int t = 0; t < NT; t++) {
        CP_WAIT1();
        __syncthreads();
        int pf = t + NSTAGE - 1;
        if (pf < NT) {
            int pj = pf >> 4, pk = pf & 15;
            load_rows_async(sA + (pf % NSTAGE) * TILE_F, qUb + pk * BK, tid);
            load_rows_async(sB + (pf % NSTAGE) * TILE_F,
                            ab + (size_t)pj * BN * HDIM + pk * BK, tid);
        }
        CP_COMMIT();
        compute_rr(sA + (t % NSTAGE) * TILE_F, sB + (t % NSTAGE) * TILE_F,
                   acc, wm, wn, lane);

        if ((t & 15) == 15) {
            // ---- epilogue for j0 = (t>>4)*BN ----
            const int j0 = (t >> 4) * BN;
            // reduction scratch aliases the just-consumed stage (free until
            // iteration t+1 re-issues into it, which is after a syncthreads)
            float* redM = sA + (t % NSTAGE) * TILE_F;
            float* redS = redM + 512;

            float am[4][2];
            #pragma unroll
            for (int nt = 0; nt < 4; nt++) {
                int c = j0 + wn * 32 + nt * 8 + (lane & 3) * 2;
                am[nt][0] = a_mask[b * LA + c];
                am[nt][1] = a_mask[b * LA + c + 1];
            }

            float cMax[4][2] = {};
            float cSum[4][2] = {};

            #pragma unroll
            for (int mt = 0; mt < 4; mt++) {
                #pragma unroll
                for (int nt = 0; nt < 4; nt++) {
                    #pragma unroll
                    for (int e = 0; e < 4; e++) {
                        float X = acc[mt][nt][e];
                        bool valid = (qm[mt][e >> 1] * am[nt][e & 1]) > 0.0f;
                        float I = valid ? __fdividef(1.0f, 1.0f + __expf(-X)) : 0.0f;
                        float ee = __expf(I);
                        rowMax[mt][e >> 1] = fmaxf(rowMax[mt][e >> 1], I);
                        rowSum[mt][e >> 1] += ee;
                        cMax[nt][e & 1] = fmaxf(cMax[nt][e & 1], I);
                        cSum[nt][e & 1] += ee;
                        acc[mt][nt][e] = 0.0f;   // reset for next j-tile
                    }
                }
            }

            __syncthreads();   // stage consumed by all warps before reuse as scratch
            #pragma unroll
            for (int nt = 0; nt < 4; nt++) {
                #pragma unroll
                for (int j = 0; j < 2; j++) {
                    float m = cMax[nt][j], s = cSum[nt][j];
                    #pragma unroll
                    for (int off = 4; off < 32; off <<= 1) {
                        m = fmaxf(m, __shfl_xor_sync(0xffffffffu, m, off));
                        s += __shfl_xor_sync(0xffffffffu, s, off);
                    }
                    if (lane < 4) {
                        int colL = wn * 32 + nt * 8 + 2 * lane + j;
                        redM[wm * 128 + colL] = m;
                        redS[wm * 128 + colL] = s;
                    }
                }
            }
            __syncthreads();
            if (tid < 128) {
                float m = fmaxf(redM[tid], redM[128 + tid]);
                float s = redS[tid] + redS[128 + tid];
                int cj = b * LA + j0 + tid;
                atomicMax(&g_colMaxBits[cj], __float_as_uint(m));
                atomicAdd(&g_colSum[cj], s);
            }
            __syncthreads();   // scratch released before next iteration writes stage
        }
    }

    // ---- final row reduction ----
    {
        float* redM = sA;
        float* redS = sA + 512;
        #pragma unroll
        for (int mt = 0; mt < 4; mt++) {
            #pragma unroll
            for (int e = 0; e < 2; e++) {
                float m = rowMax[mt][e], s = rowSum[mt][e];
                #pragma unroll
                for (int off = 1; off < 4; off <<= 1) {
                    m = fmaxf(m, __shfl_xor_sync(0xffffffffu, m, off));
                    s += __shfl_xor_sync(0xffffffffu, s, off);
                }
                if ((lane & 3) == 0) {
                    int rowL = wm * 64 + mt * 16 + (lane >> 2) + e * 8;
                    redM[wn * 128 + rowL] = m;
                    redS[wn * 128 + rowL] = s;
                }
            }
        }
        __syncthreads();
        if (tid < 128) {
            float m = redM[tid], s = redS[tid];
            #pragma unroll
            for (int w = 1; w < 4; w++) {
                m = fmaxf(m, redM[w * 128 + tid]);
                s += redS[w * 128 + tid];
            }
            g_rowAtt[b * LQ + i0 + tid] = __expf(m) / s;
        }
    }
}

// ---------------------------------------------------------------------------
// Kernel 3: weighted reductions, 8 L-segments with atomicAdd
// ---------------------------------------------------------------------------
__global__ __launch_bounds__(512) void finalize_tc(const float* __restrict__ q,
                                                   const float* __restrict__ a,
                                                   float* __restrict__ out) {
    __shared__ float attS[128];
    const int b     = blockIdx.x;
    const int which = blockIdx.y;
    const int seg   = blockIdx.z;   // 0..7
    const int h     = threadIdx.x;
    const int l0    = seg * 128;

    if (h < 128) {
        int l = l0 + h;
        if (which == 0) {
            attS[h] = g_rowAtt[b * LQ + l];
        } else {
            float m = __uint_as_float(g_colMaxBits[b * LA + l]);
            attS[h] = __expf(m) / g_colSum[b * LA + l];
        }
    }
    __syncthreads();

    const float* src = ((which == 0) ? q : a) + (size_t)b * LQ * HDIM + (size_t)l0 * HDIM;

    float a0 = 0.f, a1 = 0.f, a2 = 0.f, a3 = 0.f;
    #pragma unroll 4
    for (int l = 0; l < 128; l += 4) {
        a0 = fmaf(src[(size_t)(l + 0) * HDIM + h], attS[l + 0], a0);
        a1 = fmaf(src[(size_t)(l + 1) * HDIM + h], attS[l + 1], a1);
        a2 = fmaf(src[(size_t)(l + 2) * HDIM + h], attS[l + 2], a2);
        a3 = fmaf(src[(size_t)(l + 3) * HDIM + h], attS[l + 3], a3);
    }
    atomicAdd(&out[(size_t)which * BATCH * HDIM + b * HDIM + h], (a0 + a1) + (a2 + a3));
}

// ---------------------------------------------------------------------------
extern "C" void kernel_launch(void* const* d_in, const int* in_sizes, int n_in,
                              void* d_out, int out_size) {
    const float* q      = (const float*)d_in[0];
    const float* a      = (const float*)d_in[1];
    const float* U      = (const float*)d_in[2];
    const float* q_mask = (const float*)d_in[3];
    const float* a_mask = (const float*)d_in[4];
    float* out = (float*)d_out;

    const int smem_qU = NSTAGE * (TILE_F + UTILE_F) * sizeof(float);   // 105984
    const int smem_fx = NSTAGE * (2 * TILE_F) * sizeof(float);         // 110592
    cudaFuncSetAttribute(gemm_qU_tc, cudaFuncAttributeMaxDynamicSharedMemorySize, smem_qU);
    cudaFuncSetAttribute(fused_X_tc, cudaFuncAttributeMaxDynamicSharedMemorySize, smem_fx);

    init_stats_kernel<<<(BATCH * LA + 255) / 256, 256>>>(out, out_size);
    convert_kernel<<<4096, 256>>>(q, a, U);

    dim3 g1(HDIM / BN, (BATCH * LQ) / BM);   // (4, 256)
    gemm_qU_tc<<<g1, 256, smem_qU>>>();

    dim3 g2(LQ / BM, BATCH);                 // (8, 32)
    fused_X_tc<<<g2, 256, smem_fx>>>(q_mask, a_mask);

    dim3 g3(BATCH, 2, 8);
    finalize_tc<<<g3, 512>>>(q, a, out);
}

// round 8
// speedup vs baseline: 1.7818x; 1.7818x over previous
#include <cuda_runtime.h>
#include <cuda_bf16.h>
#include <math.h>

#define BATCH 32
#define LQ 1024
#define LA 1024
#define HDIM 512
#define HD2 (HDIM / 2)          // 256 b32 (bf16x2) per row

#define BM 128
#define BN 128
#define BK 32                   // bf16 elements per k-tile
#define NSTAGE 4
#define SROW 24                 // smem row stride in b32 (16 data + 8 pad) -> conflict-free
#define TILE_U32 (128 * SROW)   // 3072 u32 = 12 KB
#define NKT (HDIM / BK)         // 16

// Scratch (device globals: allocation inside kernel_launch is forbidden)
// bf16x2 packed, k-pair-permuted within each 16-element k-group:
//   within a k16 group, pair p (k=2p,2p+1) lives at b32 slot: p<4 ? 2p : 2(p-4)+1
__device__ unsigned g_qU[(size_t)BATCH * LQ * HD2];   // 32 MB
__device__ unsigned g_qt[(size_t)BATCH * LQ * HD2];   // 32 MB
__device__ unsigned g_at[(size_t)BATCH * LA * HD2];   // 32 MB
__device__ unsigned g_Ut[(size_t)HDIM * HD2];         // U transposed to [n][k]
__device__ float    g_rowAtt[BATCH * LQ];
__device__ unsigned g_colMaxBits[BATCH * LA];         // float bits, values >= 0
__device__ float    g_colSum[BATCH * LA];

// ---------------------------------------------------------------------------
__device__ __forceinline__ unsigned pack_bf16(float lo, float hi) {
    unsigned r;
    asm("cvt.rn.bf16x2.f32 %0, %1, %2;" : "=r"(r) : "f"(hi), "f"(lo));
    return r;
}

__device__ __forceinline__ void mma_bf16(float* d, const unsigned* a, const unsigned* b) {
    asm volatile(
        "mma.sync.aligned.m16n8k16.row.col.f32.bf16.bf16.f32 "
        "{%0,%1,%2,%3}, {%4,%5,%6,%7}, {%8,%9}, {%0,%1,%2,%3};\n"
        : "+f"(d[0]), "+f"(d[1]), "+f"(d[2]), "+f"(d[3])
        : "r"(a[0]), "r"(a[1]), "r"(a[2]), "r"(a[3]), "r"(b[0]), "r"(b[1]));
}

__device__ __forceinline__ void cp_async16(void* smem_ptr, const void* gmem) {
    unsigned s = (unsigned)__cvta_generic_to_shared(smem_ptr);
    asm volatile("cp.async.cg.shared.global [%0], [%1], 16;\n" :: "r"(s), "l"(gmem));
}
#define CP_COMMIT() asm volatile("cp.async.commit_group;\n" ::: "memory")
#define CP_WAIT()   asm volatile("cp.async.wait_group 2;\n" ::: "memory")

// Tile load: 128 rows x 16 b32 (64B) from [row][k] bf16 global (row stride HD2 b32)
__device__ __forceinline__ void load_tile_async(unsigned* sm, const unsigned* g, int tid) {
    #pragma unroll
    for (int i = 0; i < 2; i++) {
        int c = tid + i * 256;         // 0..511
        int row = c >> 2, kc = c & 3;  // 4 chunks of 16B per row
        cp_async16(sm + row * SROW + kc * 4, g + (size_t)row * HD2 + kc * 4);
    }
}

// mma over one BK=32 tile: both operands bf16 [row][k], k-pair-permuted.
// Per m16n8k16: A frag = {a0,a1,a2,a3}: a0=row g k(2c,2c+1), a1=row g+8 same,
// a2=row g k(2c+8,2c+9), a3=row g+8 same. Permuted slots (2c,2c+1) hold exactly
// (p=c, p=c+4) -> one 8B LDS gives (a0,a2). B: b0,b1 from col g the same way.
__device__ __forceinline__ void compute_rr(const unsigned* sA, const unsigned* sB,
                                           float acc[4][4][4], int wm, int wn, int lane) {
    const int c2 = 2 * (lane & 3);
    const int g4 = lane >> 2;
    #pragma unroll
    for (int ks = 0; ks < 2; ks++) {
        const int ko = ks * 8 + c2;
        unsigned bfr[4][2];
        #pragma unroll
        for (int nt = 0; nt < 4; nt++) {
            int col = wn * 32 + nt * 8 + g4;
            uint2 bv = *(const uint2*)(sB + col * SROW + ko);
            bfr[nt][0] = bv.x;
            bfr[nt][1] = bv.y;
        }
        #pragma unroll
        for (int mt = 0; mt < 4; mt++) {
            int row = wm * 64 + mt * 16 + g4;
            uint2 lo = *(const uint2*)(sA + row * SROW + ko);
            uint2 hi = *(const uint2*)(sA + (row + 8) * SROW + ko);
            unsigned afr[4] = {lo.x, hi.x, lo.y, hi.y};
            #pragma unroll
            for (int nt = 0; nt < 4; nt++)
                mma_bf16(acc[mt][nt], afr, bfr[nt]);
        }
    }
}

// ---------------------------------------------------------------------------
// Kernel 0a: zero col-stat accumulators and the output buffer
// ---------------------------------------------------------------------------
__global__ void init_stats_kernel(float* out, int out_n) {
    int i = blockIdx.x * blockDim.x + threadIdx.x;
    if (i < BATCH * LA) {
        g_colMaxBits[i] = 0u;
        g_colSum[i] = 0.0f;
    }
    if (i < out_n) out[i] = 0.0f;
}

// ---------------------------------------------------------------------------
// Kernel 0b: convert q, a -> bf16, k-pair-permuted. One thread per 16-k group.
// ---------------------------------------------------------------------------
#define NGQ (BATCH * LQ * HDIM / 16)   // 1,048,576
#define NGA (BATCH * LA * HDIM / 16)

__global__ __launch_bounds__(256) void convert_qa_kernel(const float* __restrict__ q,
                                                         const float* __restrict__ a) {
    int stride = gridDim.x * blockDim.x;
    for (int i = blockIdx.x * blockDim.x + threadIdx.x; i < NGQ + NGA; i += stride) {
        const float4* src;
        uint4* dst;
        if (i < NGQ) {
            src = (const float4*)q + (size_t)i * 4;
            dst = (uint4*)g_qt + (size_t)i * 2;
        } else {
            int j = i - NGQ;
            src = (const float4*)a + (size_t)j * 4;
            dst = (uint4*)g_at + (size_t)j * 2;
        }
        float4 v0 = src[0], v1 = src[1], v2 = src[2], v3 = src[3];
        uint4 w0, w1;
        w0.x = pack_bf16(v0.x, v0.y);   // slot0 = p0
        w0.y = pack_bf16(v2.x, v2.y);   // slot1 = p4
        w0.z = pack_bf16(v0.z, v0.w);   // slot2 = p1
        w0.w = pack_bf16(v2.z, v2.w);   // slot3 = p5
        w1.x = pack_bf16(v1.x, v1.y);   // slot4 = p2
        w1.y = pack_bf16(v3.x, v3.y);   // slot5 = p6
        w1.z = pack_bf16(v1.z, v1.w);   // slot6 = p3
        w1.w = pack_bf16(v3.z, v3.w);   // slot7 = p7
        dst[0] = w0;
        dst[1] = w1;
    }
}

// ---------------------------------------------------------------------------
// Kernel 0c: U [k][n] fp32 -> g_Ut [n][k] bf16, k-pair-permuted
// ---------------------------------------------------------------------------
__global__ __launch_bounds__(256) void convert_U_kernel(const float* __restrict__ U) {
    int i = blockIdx.x * blockDim.x + threadIdx.x;   // over HDIM * HD2
    if (i >= HDIM * HD2) return;
    int n = i >> 8;           // output row (n)
    int o = i & 255;          // b32 within row
    int g16 = o >> 3, s = o & 7;
    int p = (s & 1) ? 4 + (s >> 1) : (s >> 1);
    int k0 = g16 * 16 + 2 * p;
    g_Ut[i] = pack_bf16(U[(size_t)k0 * HDIM + n], U[(size_t)(k0 + 1) * HDIM + n]);
}

// ---------------------------------------------------------------------------
// Kernel 1: qU = q @ U  (bf16 mma, 4-stage cp.async pipeline)
// ---------------------------------------------------------------------------
__global__ __launch_bounds__(256, 2) void gemm_qU_tc() {
    extern __shared__ unsigned dsm[];
    unsigned* sA = dsm;                          // [NSTAGE][TILE_U32]
    unsigned* sB = dsm + NSTAGE * TILE_U32;

    const int tid  = threadIdx.x;
    const int lane = tid & 31;
    const int wm   = (tid >> 5) >> 2;
    const int wn   = (tid >> 5) & 3;
    const int m0   = blockIdx.y * BM;
    const int n0   = blockIdx.x * BN;

    const unsigned* gA = g_qt + (size_t)m0 * HD2;
    const unsigned* gB = g_Ut + (size_t)n0 * HD2;

    float acc[4][4][4] = {};

    #pragma unroll
    for (int s = 0; s < NSTAGE - 1; s++) {
        load_tile_async(sA + s * TILE_U32, gA + s * 16, tid);
        load_tile_async(sB + s * TILE_U32, gB + s * 16, tid);
        CP_COMMIT();
    }

    for (int kt = 0; kt < NKT; kt++) {
        CP_WAIT();
        __syncthreads();
        int pf = kt + NSTAGE - 1;
        if (pf < NKT) {
            load_tile_async(sA + (pf % NSTAGE) * TILE_U32, gA + pf * 16, tid);
            load_tile_async(sB + (pf % NSTAGE) * TILE_U32, gB + pf * 16, tid);
        }
        CP_COMMIT();
        compute_rr(sA + (kt % NSTAGE) * TILE_U32, sB + (kt % NSTAGE) * TILE_U32,
                   acc, wm, wn, lane);
    }

    // epilogue: write g_qU as bf16, k-pair-permuted along the n dimension
    #pragma unroll
    for (int mt = 0; mt < 4; mt++) {
        int row = m0 + wm * 64 + mt * 16 + (lane >> 2);
        #pragma unroll
        for (int nt = 0; nt < 4; nt++) {
            // within-group pair p = 4*(nt&1) + c -> slot 2c + (nt&1)
            int gb = ((n0 + wn * 32) >> 1) + (nt >> 1) * 8 + 2 * (lane & 3) + (nt & 1);
            g_qU[(size_t)row * HD2 + gb]       = pack_bf16(acc[mt][nt][0], acc[mt][nt][1]);
            g_qU[(size_t)(row + 8) * HD2 + gb] = pack_bf16(acc[mt][nt][2], acc[mt][nt][3]);
        }
    }
}

// ---------------------------------------------------------------------------
// Kernel 2: fused X = qU @ a^T + sigmoid/exp + row & col stats
// Flat 128-tile pipeline over (j0 x kt); epilogue every 16 tiles overlaps
// with in-flight cp.async loads of the next j-tile.
// ---------------------------------------------------------------------------
__global__ __launch_bounds__(256, 2) void fused_X_tc(const float* __restrict__ q_mask,
                                                     const float* __restrict__ a_mask) {
    extern __shared__ unsigned dsm[];
    unsigned* sA = dsm;
    unsigned* sB = dsm + NSTAGE * TILE_U32;

    const int tid  = threadIdx.x;
    const int lane = tid & 31;
    const int wm   = (tid >> 5) >> 2;
    const int wn   = (tid >> 5) & 3;
    const int b    = blockIdx.y;
    const int i0   = blockIdx.x * BM;

    const unsigned* qUb = g_qU + ((size_t)b * LQ + i0) * HD2;
    const unsigned* ab  = g_at + (size_t)b * LA * HD2;

    float qm[4][2];
    #pragma unroll
    for (int mt = 0; mt < 4; mt++) {
        int r = i0 + wm * 64 + mt * 16 + (lane >> 2);
        qm[mt][0] = q_mask[b * LQ + r];
        qm[mt][1] = q_mask[b * LQ + r + 8];
    }

    float rowMax[4][2] = {};
    float rowSum[4][2] = {};
    float acc[4][4][4] = {};

    const int NT = (LA / BN) * NKT;   // 128 total tiles

    #pragma unroll
    for (int s = 0; s < NSTAGE - 1; s++) {
        load_tile_async(sA + s * TILE_U32, qUb + s * 16, tid);
        load_tile_async(sB + s * TILE_U32, ab + s * 16, tid);   // j = 0
        CP_COMMIT();
    }

    for (int t = 0; t < NT; t++) {
        CP_WAIT();
        __syncthreads();
        int pf = t + NSTAGE - 1;
        if (pf < NT) {
            int pj = pf >> 4, pk = pf & 15;
            load_tile_async(sA + (pf % NSTAGE) * TILE_U32, qUb + pk * 16, tid);
            load_tile_async(sB + (pf % NSTAGE) * TILE_U32,
                            ab + (size_t)pj * BN * HD2 + pk * 16, tid);
        }
        CP_COMMIT();
        compute_rr(sA + (t % NSTAGE) * TILE_U32, sB + (t % NSTAGE) * TILE_U32,
                   acc, wm, wn, lane);

        if ((t & 15) == 15) {
            // ---- epilogue for j0 = (t>>4)*BN ----
            const int j0 = (t >> 4) * BN;
            // scratch aliases the just-consumed stage: it is rewritten only at
            // iteration t+1 (pf = t+NSTAGE -> stage t%NSTAGE), after a sync
            float* redM = (float*)(sA + (t % NSTAGE) * TILE_U32);
            float* redS = redM + 512;

            float am[4][2];
            #pragma unroll
            for (int nt = 0; nt < 4; nt++) {
                int c = j0 + wn * 32 + nt * 8 + (lane & 3) * 2;
                am[nt][0] = a_mask[b * LA + c];
                am[nt][1] = a_mask[b * LA + c + 1];
            }

            float cMax[4][2] = {};
            float cSum[4][2] = {};

            #pragma unroll
            for (int mt = 0; mt < 4; mt++) {
                #pragma unroll
                for (int nt = 0; nt < 4; nt++) {
                    #pragma unroll
                    for (int e = 0; e < 4; e++) {
                        float X = acc[mt][nt][e];
                        bool valid = (qm[mt][e >> 1] * am[nt][e & 1]) > 0.0f;
                        float I = valid ? __fdividef(1.0f, 1.0f + __expf(-X)) : 0.0f;
                        float ee = __expf(I);
                        rowMax[mt][e >> 1] = fmaxf(rowMax[mt][e >> 1], I);
                        rowSum[mt][e >> 1] += ee;
                        cMax[nt][e & 1] = fmaxf(cMax[nt][e & 1], I);
                        cSum[nt][e & 1] += ee;
                        acc[mt][nt][e] = 0.0f;   // reset for next j-tile
                    }
                }
            }

            __syncthreads();   // stage consumed by all warps before scratch reuse
            #pragma unroll
            for (int nt = 0; nt < 4; nt++) {
                #pragma unroll
                for (int j = 0; j < 2; j++) {
                    float m = cMax[nt][j], s = cSum[nt][j];
                    #pragma unroll
                    for (int off = 4; off < 32; off <<= 1) {
                        m = fmaxf(m, __shfl_xor_sync(0xffffffffu, m, off));
                        s += __shfl_xor_sync(0xffffffffu, s, off);
                    }
                    if (lane < 4) {
                        int colL = wn * 32 + nt * 8 + 2 * lane + j;
                        redM[wm * 128 + colL] = m;
                        redS[wm * 128 + colL] = s;
                    }
                }
            }
            __syncthreads();
            if (tid < 128) {
                float m = fmaxf(redM[tid], redM[128 + tid]);
                float s = redS[tid] + redS[128 + tid];
                int cj = b * LA + j0 + tid;
                atomicMax(&g_colMaxBits[cj], __float_as_uint(m));
                atomicAdd(&g_colSum[cj], s);
            }
            __syncthreads();   // scratch released before next iteration's loads
        }
    }

    // ---- final row reduction ----
    {
        float* redM = (float*)dsm;
        float* redS = redM + 512;
        #pragma unroll
        for (int mt = 0; mt < 4; mt++) {
            #pragma unroll
            for (int e = 0; e < 2; e++) {
                float m = rowMax[mt][e], s = rowSum[mt][e];
                #pragma unroll
                for (int off = 1; off < 4; off <<= 1) {
                    m = fmaxf(m, __shfl_xor_sync(0xffffffffu, m, off));
                    s += __shfl_xor_sync(0xffffffffu, s, off);
                }
                if ((lane & 3) == 0) {
                    int rowL = wm * 64 + mt * 16 + (lane >> 2) + e * 8;
                    redM[wn * 128 + rowL] = m;
                    redS[wn * 128 + rowL] = s;
                }
            }
        }
        __syncthreads();
        if (tid < 128) {
            float m = redM[tid], s = redS[tid];
            #pragma unroll
            for (int w = 1; w < 4; w++) {
                m = fmaxf(m, redM[w * 128 + tid]);
                s += redS[w * 128 + tid];
            }
            g_rowAtt[b * LQ + i0 + tid] = __expf(m) / s;
        }
    }
}

// ---------------------------------------------------------------------------
// Kernel 3: weighted reductions, 8 L-segments with atomicAdd (exact fp32 q/a)
// ---------------------------------------------------------------------------
__global__ __launch_bounds__(512) void finalize_tc(const float* __restrict__ q,
                                                   const float* __restrict__ a,
                                                   float* __restrict__ out) {
    __shared__ float attS[128];
    const int b     = blockIdx.x;
    const int which = blockIdx.y;
    const int seg   = blockIdx.z;   // 0..7
    const int h     = threadIdx.x;
    const int l0    = seg * 128;

    if (h < 128) {
        int l = l0 + h;
        if (which == 0) {
            attS[h] = g_rowAtt[b * LQ + l];
        } else {
            float m = __uint_as_float(g_colMaxBits[b * LA + l]);
            attS[h] = __expf(m) / g_colSum[b * LA + l];
        }
    }
    __syncthreads();

    const float* src = ((which == 0) ? q : a) + (size_t)b * LQ * HDIM + (size_t)l0 * HDIM;

    float a0 = 0.f, a1 = 0.f, a2 = 0.f, a3 = 0.f;
    #pragma unroll 4
    for (int l = 0; l < 128; l += 4) {
        a0 = fmaf(src[(size_t)(l + 0) * HDIM + h], attS[l + 0], a0);
        a1 = fmaf(src[(size_t)(l + 1) * HDIM + h], attS[l + 1], a1);
        a2 = fmaf(src[(size_t)(l + 2) * HDIM + h], attS[l + 2], a2);
        a3 = fmaf(src[(size_t)(l + 3) * HDIM + h], attS[l + 3], a3);
    }
    atomicAdd(&out[(size_t)which * BATCH * HDIM + b * HDIM + h], (a0 + a1) + (a2 + a3));
}

// ---------------------------------------------------------------------------
extern "C" void kernel_launch(void* const* d_in, const int* in_sizes, int n_in,
                              void* d_out, int out_size) {
    const float* q      = (const float*)d_in[0];
    const float* a      = (const float*)d_in[1];
    const float* U      = (const float*)d_in[2];
    const float* q_mask = (const float*)d_in[3];
    const float* a_mask = (const float*)d_in[4];
    float* out = (float*)d_out;

    const int smem_sz = NSTAGE * 2 * TILE_U32 * sizeof(unsigned);   // 98304
    cudaFuncSetAttribute(gemm_qU_tc, cudaFuncAttributeMaxDynamicSharedMemorySize, smem_sz);
    cudaFuncSetAttribute(fused_X_tc, cudaFuncAttributeMaxDynamicSharedMemorySize, smem_sz);

    init_stats_kernel<<<(BATCH * LA + 255) / 256, 256>>>(out, out_size);
    convert_qa_kernel<<<4096, 256>>>(q, a);
    convert_U_kernel<<<(HDIM * HD2 + 255) / 256, 256>>>(U);

    dim3 g1(HDIM / BN, (BATCH * LQ) / BM);   // (4, 256)
    gemm_qU_tc<<<g1, 256, smem_sz>>>();

    dim3 g2(LQ / BM, BATCH);                 // (8, 32)
    fused_X_tc<<<g2, 256, smem_sz>>>(q_mask, a_mask);

    dim3 g3(BATCH, 2, 8);
    finalize_tc<<<g3, 512>>>(q, a, out);
}

// round 11
// speedup vs baseline: 1.7826x; 1.0005x over previous
#include <cuda_runtime.h>
#include <cuda_bf16.h>
#include <math.h>

#define BATCH 32
#define LQ 1024
#define LA 1024
#define HDIM 512
#define HD2 (HDIM / 2)          // 256 b32 (bf16x2) per row

#define BM 128
#define BN 128
#define BK 32                   // bf16 elements per k-tile
#define NSTAGE 4
#define SROW 24                 // smem row stride in b32 (16 data + 8 pad) -> conflict-free
#define TILE_U32 (128 * SROW)   // 3072 u32 = 12 KB
#define NKT (HDIM / BK)         // 16

// Scratch (device globals: allocation inside kernel_launch is forbidden)
// bf16x2 packed, k-pair-permuted within each 16-element k-group:
//   within a k16 group, pair p (k=2p,2p+1) lives at b32 slot: p<4 ? 2p : 2(p-4)+1
__device__ unsigned g_qU[(size_t)BATCH * LQ * HD2];   // 32 MB
__device__ unsigned g_qt[(size_t)BATCH * LQ * HD2];   // 32 MB
__device__ unsigned g_at[(size_t)BATCH * LA * HD2];   // 32 MB
__device__ unsigned g_Ut[(size_t)HDIM * HD2];         // U transposed to [n][k]
__device__ float    g_rowAtt[BATCH * LQ];
__device__ unsigned g_colMaxBits[BATCH * LA];         // float bits, values >= 0
__device__ float    g_colSum[BATCH * LA];

// ---------------------------------------------------------------------------
__device__ __forceinline__ unsigned pack_bf16(float lo, float hi) {
    unsigned r;
    asm("cvt.rn.bf16x2.f32 %0, %1, %2;" : "=r"(r) : "f"(hi), "f"(lo));
    return r;
}

__device__ __forceinline__ void mma_bf16(float* d, const unsigned* a, const unsigned* b) {
    asm volatile(
        "mma.sync.aligned.m16n8k16.row.col.f32.bf16.bf16.f32 "
        "{%0,%1,%2,%3}, {%4,%5,%6,%7}, {%8,%9}, {%0,%1,%2,%3};\n"
        : "+f"(d[0]), "+f"(d[1]), "+f"(d[2]), "+f"(d[3])
        : "r"(a[0]), "r"(a[1]), "r"(a[2]), "r"(a[3]), "r"(b[0]), "r"(b[1]));
}

__device__ __forceinline__ void cp_async16(void* smem_ptr, const void* gmem) {
    unsigned s = (unsigned)__cvta_generic_to_shared(smem_ptr);
    asm volatile("cp.async.cg.shared.global [%0], [%1], 16;\n" :: "r"(s), "l"(gmem));
}
#define CP_COMMIT() asm volatile("cp.async.commit_group;\n" ::: "memory")
#define CP_WAIT()   asm volatile("cp.async.wait_group 2;\n" ::: "memory")

// Tile load: 128 rows x 16 b32 (64B) from [row][k] bf16 global (row stride HD2 b32)
__device__ __forceinline__ void load_tile_async(unsigned* sm, const unsigned* g, int tid) {
    #pragma unroll
    for (int i = 0; i < 2; i++) {
        int c = tid + i * 256;         // 0..511
        int row = c >> 2, kc = c & 3;  // 4 chunks of 16B per row
        cp_async16(sm + row * SROW + kc * 4, g + (size_t)row * HD2 + kc * 4);
    }
}

// mma over one BK=32 tile: both operands bf16 [row][k], k-pair-permuted.
// Per m16n8k16: A frag = {a0,a1,a2,a3}: a0=row g k(2c,2c+1), a1=row g+8 same,
// a2=row g k(2c+8,2c+9), a3=row g+8 same. Permuted slots (2c,2c+1) hold exactly
// (p=c, p=c+4) -> one 8B LDS gives (a0,a2). B: b0,b1 from col g the same way.
__device__ __forceinline__ void compute_rr(const unsigned* sA, const unsigned* sB,
                                           float acc[4][4][4], int wm, int wn, int lane) {
    const int c2 = 2 * (lane & 3);
    const int g4 = lane >> 2;
    #pragma unroll
    for (int ks = 0; ks < 2; ks++) {
        const int ko = ks * 8 + c2;
        unsigned bfr[4][2];
        #pragma unroll
        for (int nt = 0; nt < 4; nt++) {
            int col = wn * 32 + nt * 8 + g4;
            uint2 bv = *(const uint2*)(sB + col * SROW + ko);
            bfr[nt][0] = bv.x;
            bfr[nt][1] = bv.y;
        }
        #pragma unroll
        for (int mt = 0; mt < 4; mt++) {
            int row = wm * 64 + mt * 16 + g4;
            uint2 lo = *(const uint2*)(sA + row * SROW + ko);
            uint2 hi = *(const uint2*)(sA + (row + 8) * SROW + ko);
            unsigned afr[4] = {lo.x, hi.x, lo.y, hi.y};
            #pragma unroll
            for (int nt = 0; nt < 4; nt++)
                mma_bf16(acc[mt][nt], afr, bfr[nt]);
        }
    }
}

// ---------------------------------------------------------------------------
// Kernel 0a: zero col-stat accumulators and the output buffer
// ---------------------------------------------------------------------------
__global__ void init_stats_kernel(float* out, int out_n) {
    int i = blockIdx.x * blockDim.x + threadIdx.x;
    if (i < BATCH * LA) {
        g_colMaxBits[i] = 0u;
        g_colSum[i] = 0.0f;
    }
    if (i < out_n) out[i] = 0.0f;
}

// ---------------------------------------------------------------------------
// Kernel 0b: convert q, a -> bf16, k-pair-permuted. One thread per 16-k group.
// ---------------------------------------------------------------------------
#define NGQ (BATCH * LQ * HDIM / 16)   // 1,048,576
#define NGA (BATCH * LA * HDIM / 16)

__global__ __launch_bounds__(256) void convert_qa_kernel(const float* __restrict__ q,
                                                         const float* __restrict__ a) {
    int stride = gridDim.x * blockDim.x;
    for (int i = blockIdx.x * blockDim.x + threadIdx.x; i < NGQ + NGA; i += stride) {
        const float4* src;
        uint4* dst;
        if (i < NGQ) {
            src = (const float4*)q + (size_t)i * 4;
            dst = (uint4*)g_qt + (size_t)i * 2;
        } else {
            int j = i - NGQ;
            src = (const float4*)a + (size_t)j * 4;
            dst = (uint4*)g_at + (size_t)j * 2;
        }
        float4 v0 = src[0], v1 = src[1], v2 = src[2], v3 = src[3];
        uint4 w0, w1;
        w0.x = pack_bf16(v0.x, v0.y);   // slot0 = p0
        w0.y = pack_bf16(v2.x, v2.y);   // slot1 = p4
        w0.z = pack_bf16(v0.z, v0.w);   // slot2 = p1
        w0.w = pack_bf16(v2.z, v2.w);   // slot3 = p5
        w1.x = pack_bf16(v1.x, v1.y);   // slot4 = p2
        w1.y = pack_bf16(v3.x, v3.y);   // slot5 = p6
        w1.z = pack_bf16(v1.z, v1.w);   // slot6 = p3
        w1.w = pack_bf16(v3.z, v3.w);   // slot7 = p7
        dst[0] = w0;
        dst[1] = w1;
    }
}

// ---------------------------------------------------------------------------
// Kernel 0c: U [k][n] fp32 -> g_Ut [n][k] bf16, k-pair-permuted
// ---------------------------------------------------------------------------
__global__ __launch_bounds__(256) void convert_U_kernel(const float* __restrict__ U) {
    int i = blockIdx.x * blockDim.x + threadIdx.x;   // over HDIM * HD2
    if (i >= HDIM * HD2) return;
    int n = i >> 8;           // output row (n)
    int o = i & 255;          // b32 within row
    int g16 = o >> 3, s = o & 7;
    int p = (s & 1) ? 4 + (s >> 1) : (s >> 1);
    int k0 = g16 * 16 + 2 * p;
    g_Ut[i] = pack_bf16(U[(size_t)k0 * HDIM + n], U[(size_t)(k0 + 1) * HDIM + n]);
}

// ---------------------------------------------------------------------------
// Kernel 1: qU = q @ U  (bf16 mma, 4-stage cp.async pipeline)
// ---------------------------------------------------------------------------
__global__ __launch_bounds__(256, 2) void gemm_qU_tc() {
    extern __shared__ unsigned dsm[];
    unsigned* sA = dsm;                          // [NSTAGE][TILE_U32]
    unsigned* sB = dsm + NSTAGE * TILE_U32;

    const int tid  = threadIdx.x;
    const int lane = tid & 31;
    const int wm   = (tid >> 5) >> 2;
    const int wn   = (tid >> 5) & 3;
    const int m0   = blockIdx.y * BM;
    const int n0   = blockIdx.x * BN;

    const unsigned* gA = g_qt + (size_t)m0 * HD2;
    const unsigned* gB = g_Ut + (size_t)n0 * HD2;

    float acc[4][4][4] = {};

    #pragma unroll
    for (int s = 0; s < NSTAGE - 1; s++) {
        load_tile_async(sA + s * TILE_U32, gA + s * 16, tid);
        load_tile_async(sB + s * TILE_U32, gB + s * 16, tid);
        CP_COMMIT();
    }

    for (int kt = 0; kt < NKT; kt++) {
        CP_WAIT();
        __syncthreads();
        int pf = kt + NSTAGE - 1;
        if (pf < NKT) {
            load_tile_async(sA + (pf % NSTAGE) * TILE_U32, gA + pf * 16, tid);
            load_tile_async(sB + (pf % NSTAGE) * TILE_U32, gB + pf * 16, tid);
        }
        CP_COMMIT();
        compute_rr(sA + (kt % NSTAGE) * TILE_U32, sB + (kt % NSTAGE) * TILE_U32,
                   acc, wm, wn, lane);
    }

    // epilogue: write g_qU as bf16, k-pair-permuted along the n dimension
    #pragma unroll
    for (int mt = 0; mt < 4; mt++) {
        int row = m0 + wm * 64 + mt * 16 + (lane >> 2);
        #pragma unroll
        for (int nt = 0; nt < 4; nt++) {
            // within-group pair p = 4*(nt&1) + c -> slot 2c + (nt&1)
            int gb = ((n0 + wn * 32) >> 1) + (nt >> 1) * 8 + 2 * (lane & 3) + (nt & 1);
            g_qU[(size_t)row * HD2 + gb]       = pack_bf16(acc[mt][nt][0], acc[mt][nt][1]);
            g_qU[(size_t)(row + 8) * HD2 + gb] = pack_bf16(acc[mt][nt][2], acc[mt][nt][3]);
        }
    }
}

// ---------------------------------------------------------------------------
// Kernel 2: fused X = qU @ a^T + sigmoid/exp + row & col stats
// Flat 128-tile pipeline over (j0 x kt); epilogue every 16 tiles overlaps
// with in-flight cp.async loads of the next j-tile.
// ---------------------------------------------------------------------------
__global__ __launch_bounds__(256, 2) void fused_X_tc(const float* __restrict__ q_mask,
                                                     const float* __restrict__ a_mask) {
    extern __shared__ unsigned dsm[];
    unsigned* sA = dsm;
    unsigned* sB = dsm + NSTAGE * TILE_U32;

    const int tid  = threadIdx.x;
    const int lane = tid & 31;
    const int wm   = (tid >> 5) >> 2;
    const int wn   = (tid >> 5) & 3;
    const int b    = blockIdx.y;
    const int i0   = blockIdx.x * BM;

    const unsigned* qUb = g_qU + ((size_t)b * LQ + i0) * HD2;
    const unsigned* ab  = g_at + (size_t)b * LA * HD2;

    float qm[4][2];
    #pragma unroll
    for (int mt = 0; mt < 4; mt++) {
        int r = i0 + wm * 64 + mt * 16 + (lane >> 2);
        qm[mt][0] = q_mask[b * LQ + r];
        qm[mt][1] = q_mask[b * LQ + r + 8];
    }

    float rowMax[4][2] = {};
    float rowSum[4][2] = {};
    float acc[4][4][4] = {};

    const int NT = (LA / BN) * NKT;   // 128 total tiles

    #pragma unroll
    for (int s = 0; s < NSTAGE - 1; s++) {
        load_tile_async(sA + s * TILE_U32, qUb + s * 16, tid);
        load_tile_async(sB + s * TILE_U32, ab + s * 16, tid);   // j = 0
        CP_COMMIT();
    }

    for (int t = 0; t < NT; t++) {
        CP_WAIT();
        __syncthreads();
        int pf = t + NSTAGE - 1;
        if (pf < NT) {
            int pj = pf >> 4, pk = pf & 15;
            load_tile_async(sA + (pf % NSTAGE) * TILE_U32, qUb + pk * 16, tid);
            load_tile_async(sB + (pf % NSTAGE) * TILE_U32,
                            ab + (size_t)pj * BN * HD2 + pk * 16, tid);
        }
        CP_COMMIT();
        compute_rr(sA + (t % NSTAGE) * TILE_U32, sB + (t % NSTAGE) * TILE_U32,
                   acc, wm, wn, lane);

        if ((t & 15) == 15) {
            // ---- epilogue for j0 = (t>>4)*BN ----
            const int j0 = (t >> 4) * BN;
            // scratch aliases the just-consumed stage: it is rewritten only at
            // iteration t+1 (pf = t+NSTAGE -> stage t%NSTAGE), after a sync
            float* redM = (float*)(sA + (t % NSTAGE) * TILE_U32);
            float* redS = redM + 512;

            float am[4][2];
            #pragma unroll
            for (int nt = 0; nt < 4; nt++) {
                int c = j0 + wn * 32 + nt * 8 + (lane & 3) * 2;
                am[nt][0] = a_mask[b * LA + c];
                am[nt][1] = a_mask[b * LA + c + 1];
            }

            float cMax[4][2] = {};
            float cSum[4][2] = {};

            #pragma unroll
            for (int mt = 0; mt < 4; mt++) {
                #pragma unroll
                for (int nt = 0; nt < 4; nt++) {
                    #pragma unroll
                    for (int e = 0; e < 4; e++) {
                        float X = acc[mt][nt][e];
                        bool valid = (qm[mt][e >> 1] * am[nt][e & 1]) > 0.0f;
                        float I = valid ? __fdividef(1.0f, 1.0f + __expf(-X)) : 0.0f;
                        float ee = __expf(I);
                        rowMax[mt][e >> 1] = fmaxf(rowMax[mt][e >> 1], I);
                        rowSum[mt][e >> 1] += ee;
                        cMax[nt][e & 1] = fmaxf(cMax[nt][e & 1], I);
                        cSum[nt][e & 1] += ee;
                        acc[mt][nt][e] = 0.0f;   // reset for next j-tile
                    }
                }
            }

            __syncthreads();   // stage consumed by all warps before scratch reuse
            #pragma unroll
            for (int nt = 0; nt < 4; nt++) {
                #pragma unroll
                for (int j = 0; j < 2; j++) {
                    float m = cMax[nt][j], s = cSum[nt][j];
                    #pragma unroll
                    for (int off = 4; off < 32; off <<= 1) {
                        m = fmaxf(m, __shfl_xor_sync(0xffffffffu, m, off));
                        s += __shfl_xor_sync(0xffffffffu, s, off);
                    }
                    if (lane < 4) {
                        int colL = wn * 32 + nt * 8 + 2 * lane + j;
                        redM[wm * 128 + colL] = m;
                        redS[wm * 128 + colL] = s;
                    }
                }
            }
            __syncthreads();
            if (tid < 128) {
                float m = fmaxf(redM[tid], redM[128 + tid]);
                float s = redS[tid] + redS[128 + tid];
                int cj = b * LA + j0 + tid;
                atomicMax(&g_colMaxBits[cj], __float_as_uint(m));
                atomicAdd(&g_colSum[cj], s);
            }
            __syncthreads();   // scratch released before next iteration's loads
        }
    }

    // ---- final row reduction ----
    {
        float* redM = (float*)dsm;
        float* redS = redM + 512;
        #pragma unroll
        for (int mt = 0; mt < 4; mt++) {
            #pragma unroll
            for (int e = 0; e < 2; e++) {
                float m = rowMax[mt][e], s = rowSum[mt][e];
                #pragma unroll
                for (int off = 1; off < 4; off <<= 1) {
                    m = fmaxf(m, __shfl_xor_sync(0xffffffffu, m, off));
                    s += __shfl_xor_sync(0xffffffffu, s, off);
                }
                if ((lane & 3) == 0) {
                    int rowL = wm * 64 + mt * 16 + (lane >> 2) + e * 8;
                    redM[wn * 128 + rowL] = m;
                    redS[wn * 128 + rowL] = s;
                }
            }
        }
        __syncthreads();
        if (tid < 128) {
            float m = redM[tid], s = redS[tid];
            #pragma unroll
            for (int w = 1; w < 4; w++) {
                m = fmaxf(m, redM[w * 128 + tid]);
                s += redS[w * 128 + tid];
            }
            g_rowAtt[b * LQ + i0 + tid] = __expf(m) / s;
        }
    }
}

// ---------------------------------------------------------------------------
// Kernel 3: weighted reductions, 8 L-segments with atomicAdd (exact fp32 q/a)
// ---------------------------------------------------------------------------
__global__ __launch_bounds__(512) void finalize_tc(const float* __restrict__ q,
                                                   const float* __restrict__ a,
                                                   float* __restrict__ out) {
    __shared__ float attS[128];
    const int b     = blockIdx.x;
    const int which = blockIdx.y;
    const int seg   = blockIdx.z;   // 0..7
    const int h     = threadIdx.x;
    const int l0    = seg * 128;

    if (h < 128) {
        int l = l0 + h;
        if (which == 0) {
            attS[h] = g_rowAtt[b * LQ + l];
        } else {
            float m = __uint_as_float(g_colMaxBits[b * LA + l]);
            attS[h] = __expf(m) / g_colSum[b * LA + l];
        }
    }
    __syncthreads();

    const float* src = ((which == 0) ? q : a) + (size_t)b * LQ * HDIM + (size_t)l0 * HDIM;

    float a0 = 0.f, a1 = 0.f, a2 = 0.f, a3 = 0.f;
    #pragma unroll 4
    for (int l = 0; l < 128; l += 4) {
        a0 = fmaf(src[(size_t)(l + 0) * HDIM + h], attS[l + 0], a0);
        a1 = fmaf(src[(size_t)(l + 1) * HDIM + h], attS[l + 1], a1);
        a2 = fmaf(src[(size_t)(l + 2) * HDIM + h], attS[l + 2], a2);
        a3 = fmaf(src[(size_t)(l + 3) * HDIM + h], attS[l + 3], a3);
    }
    atomicAdd(&out[(size_t)which * BATCH * HDIM + b * HDIM + h], (a0 + a1) + (a2 + a3));
}

// ---------------------------------------------------------------------------
extern "C" void kernel_launch(void* const* d_in, const int* in_sizes, int n_in,
                              void* d_out, int out_size) {
    const float* q      = (const float*)d_in[0];
    const float* a      = (const float*)d_in[1];
    const float* U      = (const float*)d_in[2];
    const float* q_mask = (const float*)d_in[3];
    const float* a_mask = (const float*)d_in[4];
    float* out = (float*)d_out;

    const int smem_sz = NSTAGE * 2 * TILE_U32 * sizeof(unsigned);   // 98304
    cudaFuncSetAttribute(gemm_qU_tc, cudaFuncAttributeMaxDynamicSharedMemorySize, smem_sz);
    cudaFuncSetAttribute(fused_X_tc, cudaFuncAttributeMaxDynamicSharedMemorySize, smem_sz);

    init_stats_kernel<<<(BATCH * LA + 255) / 256, 256>>>(out, out_size);
    convert_qa_kernel<<<4096, 256>>>(q, a);
    convert_U_kernel<<<(HDIM * HD2 + 255) / 256, 256>>>(U);

    dim3 g1(HDIM / BN, (BATCH * LQ) / BM);   // (4, 256)
    gemm_qU_tc<<<g1, 256, smem_sz>>>();

    dim3 g2(LQ / BM, BATCH);                 // (8, 32)
    fused_X_tc<<<g2, 256, smem_sz>>>(q_mask, a_mask);

    dim3 g3(BATCH, 2, 8);
    finalize_tc<<<g3, 512>>>(q, a, out);
}